// round 12
// baseline (speedup 1.0000x reference)
#include <cuda_runtime.h>
#include <cstdint>

// Chamfer distance via exact grid NN search — 2-kernel version.
// pred/gt: [4, 8192, 3] fp32, N(0,1). Output: scalar fp32.
//
// R11: tiny launches cost ~2-4us each inside the graph. Collapse to
// [build, query]: build zeroes the accumulators, query does block-level
// reduction (256 block atomics instead of 2048 warp atomics on ONE L2
// address) and the last block converts+writes the scalar (threadfence +
// done-counter; integer fixed-point sum -> deterministic).

#define NPTS   8192
#define BATCH  4
#define NGRIDS 8                     // batch x {pred,gt}
#define GB     32
#define GB3    (GB * GB * GB)        // 32768
#define SROW   (GB3 + 4)             // row stride, %4==0 -> int4 aligned
#define XMIN   (-6.0f)
#define H      0.375f                // 12/32, exactly representable
#define INVH   (GB / 12.0f)
#define RBSAFE 0.37495f              // slightly < H: conservative cube bound
#define NQ     (2 * BATCH * NPTS)    // 65536
#define QBLK   256
#define QGRID  (NQ / QBLK)           // 256 blocks
#define SCALE  4294967296.0          // 2^32 fixed-point for the sum

__device__ int                g_start[NGRIDS][SROW];
__device__ float4             g_pts[NGRIDS][NPTS];
__device__ unsigned long long g_sum;
__device__ unsigned int       g_done;

__device__ __forceinline__ int bin1(float v) {
    int c = (int)floorf((v - XMIN) * INVH);
    return min(GB - 1, max(0, c));
}

// ---- K1: fused build. One block per grid: smem histogram -> scan -> CSR ----
__global__ __launch_bounds__(1024, 1)
void cd_build(const float* __restrict__ pred, const float* __restrict__ gt) {
    extern __shared__ int cnt[];            // GB3 ints = 128 KB
    __shared__ int warp_part[32];
    const int g   = blockIdx.x;             // 0..7 = (b<<1)|src
    const int tid = threadIdx.x;
    const int lid = tid & 31, wid = tid >> 5;
    const int s_  = g & 1, b = g >> 1;
    const float* src = (s_ ? gt : pred) + (size_t)b * NPTS * 3;

    if (g == 0 && tid == 0) { g_sum = 0ull; g_done = 0u; }

    #pragma unroll
    for (int k = 0; k < 8; k++)
        ((int4*)cnt)[tid + k * 1024] = make_int4(0, 0, 0, 0);
    __syncthreads();

    // count (stash cell ids for the scatter pass)
    int cells[NPTS / 1024];
    #pragma unroll
    for (int k = 0; k < NPTS / 1024; k++) {
        int i = tid + k * 1024;
        const float* p = src + (size_t)i * 3;
        int cx = bin1(p[0]), cy = bin1(p[1]), cz = bin1(p[2]);
        cells[k] = (cz * GB + cy) * GB + cx;
        atomicAdd(&cnt[cells[k]], 1);
    }
    __syncthreads();

    // block-wide exclusive scan of per-thread sums (32 cells each), shfl-based
    int s = 0;
    int4 c4s[8];
    #pragma unroll
    for (int k = 0; k < 8; k++) {
        c4s[k] = ((int4*)cnt)[tid * 8 + k];
        s += c4s[k].x + c4s[k].y + c4s[k].z + c4s[k].w;
    }
    int incl = s;
    #pragma unroll
    for (int off = 1; off < 32; off <<= 1) {
        int v = __shfl_up_sync(0xFFFFFFFFu, incl, off);
        if (lid >= off) incl += v;
    }
    if (lid == 31) warp_part[wid] = incl;
    __syncthreads();
    if (wid == 0) {
        int w = warp_part[lid];
        int wincl = w;
        #pragma unroll
        for (int off = 1; off < 32; off <<= 1) {
            int v = __shfl_up_sync(0xFFFFFFFFu, wincl, off);
            if (lid >= off) wincl += v;
        }
        warp_part[lid] = wincl - w;              // exclusive warp offsets
    }
    __syncthreads();
    int run = warp_part[wid] + (incl - s);       // exclusive prefix for this thread

    // rewrite smem counts -> exclusive starts (= scatter cursors), mirror to gmem
    int4* gst = (int4*)&g_start[g][tid * 32];    // SROW%4==0 -> aligned
    #pragma unroll
    for (int k = 0; k < 8; k++) {
        int4 c4 = c4s[k];
        int4 o;
        o.x = run;
        o.y = o.x + c4.x;
        o.z = o.y + c4.y;
        o.w = o.z + c4.z;
        run = o.w + c4.w;
        gst[k] = o;
        ((int4*)cnt)[tid * 8 + k] = o;
    }
    if (tid == 1023) g_start[g][GB3] = run;      // == NPTS
    __syncthreads();

    // scatter (reload coords; L1/L2-hot)
    #pragma unroll
    for (int k = 0; k < NPTS / 1024; k++) {
        int i = tid + k * 1024;
        const float* p = src + (size_t)i * 3;
        float x = p[0], y = p[1], z = p[2];
        int pos = atomicAdd(&cnt[cells[k]], 1);
        g_pts[g][pos] = make_float4(x, y, z, 0.0f);
    }
}

// ---- K2: exact NN per query + block reduction + last-block finalize ----
__global__ __launch_bounds__(QBLK)
void cd_query(float* __restrict__ out) {
    int t = blockIdx.x * QBLK + threadIdx.x;     // 65536
    int i = t & (NPTS - 1);
    int b = (t >> 13) & (BATCH - 1);
    int dir = t >> 15;

    const int qg = (b << 1) | dir;          // query grid (sorted copy of own set)
    const int dg = qg ^ 1;                  // database grid (opposite set)

    float4 qv = g_pts[qg][i];
    const float qx = qv.x, qy = qv.y, qz = qv.z;
    const int cx = bin1(qx), cy = bin1(qy), cz = bin1(qz);

    const int*    start = g_start[dg];
    const float4* pts   = g_pts[dg];

    float m0 = __int_as_float(0x7F800000);
    float m1 = __int_as_float(0x7F800000);

    auto scan_span = [&](int s, int e) {
        int k = s;
        for (; k + 1 < e; k += 2) {
            float4 p = __ldg(&pts[k]);
            float4 q = __ldg(&pts[k + 1]);
            float dx = qx - p.x, dy = qy - p.y, dz = qz - p.z;
            m0 = fminf(m0, fmaf(dx, dx, fmaf(dy, dy, dz * dz)));
            float ex = qx - q.x, ey = qy - q.y, ez = qz - q.z;
            m1 = fminf(m1, fmaf(ex, ex, fmaf(ey, ey, ez * ez)));
        }
        if (k < e) {
            float4 p = __ldg(&pts[k]);
            float dx = qx - p.x, dy = qy - p.y, dz = qz - p.z;
            m0 = fminf(m0, fmaf(dx, dx, fmaf(dy, dy, dz * dz)));
        }
    };

    // batch ALL radius-1 descriptors upfront (MLP=20, one L2 latency)
    const int xa = max(cx - 1, 0);
    const int xb = min(cx + 1, GB - 1);
    const int cb = (cz * GB + cy) * GB;
    int s_[9], e_[9];
    #pragma unroll
    for (int j = 0; j < 9; j++) {
        int y = cy + (j % 3) - 1;
        int z = cz + (j / 3) - 1;
        bool ok = ((unsigned)y < GB) & ((unsigned)z < GB);
        int base = (z * GB + y) * GB;
        s_[j] = ok ? __ldg(&start[base + xa])     : 0;
        e_[j] = ok ? __ldg(&start[base + xb + 1]) : 0;
    }
    int so = __ldg(&start[cb + cx]), eo = __ldg(&start[cb + cx + 1]);

    // own cell first
    scan_span(so, eo);
    float best = fminf(m0, m1);

    // per-axis squared gaps to the 6 cell faces (clamped points lie beyond)
    const float x0 = XMIN + cx * H, y0 = XMIN + cy * H, z0 = XMIN + cz * H;
    const float gxl = (qx - x0) * (qx - x0), gxr = (x0 + H - qx) * (x0 + H - qx);
    const float gyl = (qy - y0) * (qy - y0), gyr = (y0 + H - qy) * (y0 + H - qy);
    const float gzl = (qz - z0) * (qz - z0), gzr = (z0 + H - qz) * (z0 + H - qz);

    // radius-1 rows, pruned by exact slab bounds (descriptors already resident)
    #pragma unroll
    for (int j = 0; j < 9; j++) {
        const int oy = j % 3 - 1, oz = j / 3 - 1;
        const float rowb = (oy < 0 ? gyl : oy > 0 ? gyr : 0.0f)
                         + (oz < 0 ? gzl : oz > 0 ? gzr : 0.0f);
        if (rowb >= best) continue;
        if (oy == 0 && oz == 0) {
            if (cx > 0      && gxl < best) scan_span(s_[4], so);
            if (cx < GB - 1 && gxr < best) scan_span(eo, e_[4]);
        } else {
            scan_span(s_[j], e_[j]);
        }
        best = fminf(m0, m1);
    }

    // rare tail: expand full cube until the exact Chebyshev bound holds
    int r = 1;
    float rbound = RBSAFE;
    while (best > rbound * rbound && r < GB) {
        r++;
        rbound = (float)r * RBSAFE;
        const int z0i = max(cz - r, 0), z1i = min(cz + r, GB - 1);
        const int y0i = max(cy - r, 0), y1i = min(cy + r, GB - 1);
        const int xra = max(cx - r, 0), xrb = min(cx + r, GB - 1);
        for (int z = z0i; z <= z1i; z++)
            for (int y = y0i; y <= y1i; y++) {
                const int rb = (z * GB + y) * GB;
                scan_span(__ldg(&start[rb + xra]), __ldg(&start[rb + xrb + 1]));
            }
        best = fminf(m0, m1);
    }

    // ---- fixed-point block reduction -> one atomic per block ----
    __shared__ unsigned long long wsum[QBLK / 32];
    unsigned long long v = (unsigned long long)((double)best * SCALE + 0.5);
    #pragma unroll
    for (int off = 16; off > 0; off >>= 1)
        v += __shfl_down_sync(0xFFFFFFFFu, v, off);
    const int lid = threadIdx.x & 31, wid = threadIdx.x >> 5;
    if (lid == 0) wsum[wid] = v;
    __syncthreads();
    if (wid == 0) {
        unsigned long long bv = (lid < QBLK / 32) ? wsum[lid] : 0ull;
        #pragma unroll
        for (int off = QBLK / 64; off > 0; off >>= 1)
            bv += __shfl_down_sync(0xFFFFFFFFu, bv, off);
        if (lid == 0) {
            atomicAdd(&g_sum, bv);
            __threadfence();
            unsigned int old = atomicAdd(&g_done, 1u);
            if (old == QGRID - 1) {
                unsigned long long total = atomicAdd(&g_sum, 0ull);
                out[0] = (float)((double)total / (SCALE * (double)(BATCH * NPTS)));
            }
        }
    }
}

extern "C" void kernel_launch(void* const* d_in, const int* in_sizes, int n_in,
                              void* d_out, int out_size) {
    const float* pred = (const float*)d_in[0];
    const float* gt   = (const float*)d_in[1];
    float* out        = (float*)d_out;

    static int configured = 0;
    if (!configured) {
        cudaFuncSetAttribute(cd_build, cudaFuncAttributeMaxDynamicSharedMemorySize,
                             GB3 * (int)sizeof(int));
        configured = 1;
    }

    cd_build<<<NGRIDS, 1024, GB3 * sizeof(int)>>>(pred, gt);
    cd_query<<<QGRID, QBLK>>>(out);
}

// round 14
// speedup vs baseline: 1.0699x; 1.0699x over previous
#include <cuda_runtime.h>
#include <cstdint>

// Chamfer distance via exact grid NN search — 4 lanes per query.
// pred/gt: [4, 8192, 3] fp32, N(0,1). Output: scalar fp32.
//
// R12 profile: cd_query occ 18.3% / issue 19.5%, all pipes idle -> grid-
// limited latency exposure. Fix: 4-lane subgroups per query (8192 warps).
// R13 fix: group shuffles must use the 4-lane group mask -- the pruning
// control flow is uniform within a group but DIVERGENT across groups, so
// full-warp-mask shfl_xor was UB (illegal instruction/memory trap).

#define NPTS   8192
#define BATCH  4
#define NGRIDS 8                     // batch x {pred,gt}
#define GB     32
#define GB3    (GB * GB * GB)        // 32768
#define SROW   (GB3 + 4)             // row stride, %4==0 -> int4 aligned
#define XMIN   (-6.0f)
#define H      0.375f                // 12/32, exactly representable
#define INVH   (GB / 12.0f)
#define RBSAFE 0.37495f              // slightly < H: conservative cube bound
#define NQ     (2 * BATCH * NPTS)    // 65536
#define QBLK   256
#define QGRID  (NQ * 4 / QBLK)       // 1024 blocks (4 threads per query)
#define SCALE  4294967296.0          // 2^32 fixed-point for the sum

__device__ int                g_start[NGRIDS][SROW];
__device__ float4             g_pts[NGRIDS][NPTS];
__device__ unsigned long long g_sum;
__device__ unsigned int       g_done;

__device__ __forceinline__ int bin1(float v) {
    int c = (int)floorf((v - XMIN) * INVH);
    return min(GB - 1, max(0, c));
}

// ---- K1: fused build. One block per grid: smem histogram -> scan -> CSR ----
__global__ __launch_bounds__(1024, 1)
void cd_build(const float* __restrict__ pred, const float* __restrict__ gt) {
    extern __shared__ int cnt[];            // GB3 ints = 128 KB
    __shared__ int warp_part[32];
    const int g   = blockIdx.x;             // 0..7 = (b<<1)|src
    const int tid = threadIdx.x;
    const int lid = tid & 31, wid = tid >> 5;
    const int s_  = g & 1, b = g >> 1;
    const float* src = (s_ ? gt : pred) + (size_t)b * NPTS * 3;

    if (g == 0 && tid == 0) { g_sum = 0ull; g_done = 0u; }

    #pragma unroll
    for (int k = 0; k < 8; k++)
        ((int4*)cnt)[tid + k * 1024] = make_int4(0, 0, 0, 0);
    __syncthreads();

    // count (stash cell ids for the scatter pass)
    int cells[NPTS / 1024];
    #pragma unroll
    for (int k = 0; k < NPTS / 1024; k++) {
        int i = tid + k * 1024;
        const float* p = src + (size_t)i * 3;
        int cx = bin1(p[0]), cy = bin1(p[1]), cz = bin1(p[2]);
        cells[k] = (cz * GB + cy) * GB + cx;
        atomicAdd(&cnt[cells[k]], 1);
    }
    __syncthreads();

    // block-wide exclusive scan of per-thread sums (32 cells each), shfl-based
    int s = 0;
    int4 c4s[8];
    #pragma unroll
    for (int k = 0; k < 8; k++) {
        c4s[k] = ((int4*)cnt)[tid * 8 + k];
        s += c4s[k].x + c4s[k].y + c4s[k].z + c4s[k].w;
    }
    int incl = s;
    #pragma unroll
    for (int off = 1; off < 32; off <<= 1) {
        int v = __shfl_up_sync(0xFFFFFFFFu, incl, off);
        if (lid >= off) incl += v;
    }
    if (lid == 31) warp_part[wid] = incl;
    __syncthreads();
    if (wid == 0) {
        int w = warp_part[lid];
        int wincl = w;
        #pragma unroll
        for (int off = 1; off < 32; off <<= 1) {
            int v = __shfl_up_sync(0xFFFFFFFFu, wincl, off);
            if (lid >= off) wincl += v;
        }
        warp_part[lid] = wincl - w;              // exclusive warp offsets
    }
    __syncthreads();
    int run = warp_part[wid] + (incl - s);       // exclusive prefix for this thread

    // rewrite smem counts -> exclusive starts (= scatter cursors), mirror to gmem
    int4* gst = (int4*)&g_start[g][tid * 32];    // SROW%4==0 -> aligned
    #pragma unroll
    for (int k = 0; k < 8; k++) {
        int4 c4 = c4s[k];
        int4 o;
        o.x = run;
        o.y = o.x + c4.x;
        o.z = o.y + c4.y;
        o.w = o.z + c4.z;
        run = o.w + c4.w;
        gst[k] = o;
        ((int4*)cnt)[tid * 8 + k] = o;
    }
    if (tid == 1023) g_start[g][GB3] = run;      // == NPTS
    __syncthreads();

    // scatter (reload coords; L1/L2-hot)
    #pragma unroll
    for (int k = 0; k < NPTS / 1024; k++) {
        int i = tid + k * 1024;
        const float* p = src + (size_t)i * 3;
        float x = p[0], y = p[1], z = p[2];
        int pos = atomicAdd(&cnt[cells[k]], 1);
        g_pts[g][pos] = make_float4(x, y, z, 0.0f);
    }
}

// ---- K2: exact NN, 4 lanes per query, block reduce + last-block finalize ----
__global__ __launch_bounds__(QBLK)
void cd_query(float* __restrict__ out) {
    const int t   = blockIdx.x * QBLK + threadIdx.x;   // 262144
    const int q   = t >> 2;                            // query id
    const int sub = t & 3;                             // lane within 4-group
    const int i   = q & (NPTS - 1);
    const int b   = (q >> 13) & (BATCH - 1);
    const int dir = q >> 15;

    // mask naming exactly the 4 convergent lanes of this group
    const unsigned gmask = 0xFu << ((threadIdx.x & 31) & ~3);

    const int qg = (b << 1) | dir;          // query grid (sorted copy of own set)
    const int dg = qg ^ 1;                  // database grid (opposite set)

    float4 qv = g_pts[qg][i];
    const float qx = qv.x, qy = qv.y, qz = qv.z;
    const int cx = bin1(qx), cy = bin1(qy), cz = bin1(qz);

    const int*    start = g_start[dg];
    const float4* pts   = g_pts[dg];

    float m = __int_as_float(0x7F800000);   // lane-partial min

    auto scan_span = [&](int s, int e) {    // lanes take k = s+sub, s+sub+4, ...
        for (int k = s + sub; k < e; k += 4) {
            float4 p = __ldg(&pts[k]);
            float dx = qx - p.x, dy = qy - p.y, dz = qz - p.z;
            m = fminf(m, fmaf(dx, dx, fmaf(dy, dy, dz * dz)));
        }
    };
    auto gmin = [&]() {                      // combined min over the 4-group
        float v = m;
        v = fminf(v, __shfl_xor_sync(gmask, v, 1));
        v = fminf(v, __shfl_xor_sync(gmask, v, 2));
        return v;
    };

    // batch ALL radius-1 descriptors upfront (broadcast loads, one L2 latency)
    const int xa = max(cx - 1, 0);
    const int xb = min(cx + 1, GB - 1);
    const int cb = (cz * GB + cy) * GB;
    int s_[9], e_[9];
    #pragma unroll
    for (int j = 0; j < 9; j++) {
        int y = cy + (j % 3) - 1;
        int z = cz + (j / 3) - 1;
        bool ok = ((unsigned)y < GB) & ((unsigned)z < GB);
        int base = (z * GB + y) * GB;
        s_[j] = ok ? __ldg(&start[base + xa])     : 0;
        e_[j] = ok ? __ldg(&start[base + xb + 1]) : 0;
    }
    const int so = __ldg(&start[cb + cx]), eo = __ldg(&start[cb + cx + 1]);

    // own cell first
    scan_span(so, eo);
    float best = gmin();

    // per-axis squared gaps to the 6 cell faces (clamped points lie beyond)
    const float x0 = XMIN + cx * H, y0 = XMIN + cy * H, z0 = XMIN + cz * H;
    const float gxl = (qx - x0) * (qx - x0), gxr = (x0 + H - qx) * (x0 + H - qx);
    const float gyl = (qy - y0) * (qy - y0), gyr = (y0 + H - qy) * (y0 + H - qy);
    const float gzl = (qz - z0) * (qz - z0), gzr = (z0 + H - qz) * (z0 + H - qz);

    // radius-1 rows, pruned by exact slab bounds (descriptors already resident).
    // All branch conditions are group-uniform -> the 4 lanes stay convergent.
    #pragma unroll
    for (int j = 0; j < 9; j++) {
        const int oy = j % 3 - 1, oz = j / 3 - 1;
        const float rowb = (oy < 0 ? gyl : oy > 0 ? gyr : 0.0f)
                         + (oz < 0 ? gzl : oz > 0 ? gzr : 0.0f);
        if (rowb >= best) continue;
        if (oy == 0 && oz == 0) {
            if (cx > 0      && gxl < best) scan_span(s_[4], so);
            if (cx < GB - 1 && gxr < best) scan_span(eo, e_[4]);
        } else {
            scan_span(s_[j], e_[j]);
        }
        best = gmin();
    }

    // rare tail: expand full cube until the exact Chebyshev bound holds
    int r = 1;
    float rbound = RBSAFE;
    while (best > rbound * rbound && r < GB) {
        r++;
        rbound = (float)r * RBSAFE;
        const int z0i = max(cz - r, 0), z1i = min(cz + r, GB - 1);
        const int y0i = max(cy - r, 0), y1i = min(cy + r, GB - 1);
        const int xra = max(cx - r, 0), xrb = min(cx + r, GB - 1);
        for (int z = z0i; z <= z1i; z++)
            for (int y = y0i; y <= y1i; y++) {
                const int rb = (z * GB + y) * GB;
                scan_span(__ldg(&start[rb + xra]), __ldg(&start[rb + xrb + 1]));
            }
        best = gmin();
    }

    // ---- fixed-point block reduction -> one atomic per block ----
    __syncwarp();                            // reconverge full warp after divergence
    __shared__ unsigned long long wsum[QBLK / 32];
    unsigned long long v = (sub == 0)
        ? (unsigned long long)((double)best * SCALE + 0.5) : 0ull;
    #pragma unroll
    for (int off = 16; off > 0; off >>= 1)
        v += __shfl_down_sync(0xFFFFFFFFu, v, off);
    const int lid = threadIdx.x & 31, wid = threadIdx.x >> 5;
    if (lid == 0) wsum[wid] = v;
    __syncthreads();
    if (wid == 0) {
        unsigned long long bv = (lid < QBLK / 32) ? wsum[lid] : 0ull;
        #pragma unroll
        for (int off = QBLK / 64; off > 0; off >>= 1)
            bv += __shfl_down_sync(0xFFFFFFFFu, bv, off);
        if (lid == 0) {
            atomicAdd(&g_sum, bv);
            __threadfence();
            unsigned int old = atomicAdd(&g_done, 1u);
            if (old == QGRID - 1) {
                unsigned long long total = atomicAdd(&g_sum, 0ull);
                out[0] = (float)((double)total / (SCALE * (double)(BATCH * NPTS)));
            }
        }
    }
}

extern "C" void kernel_launch(void* const* d_in, const int* in_sizes, int n_in,
                              void* d_out, int out_size) {
    const float* pred = (const float*)d_in[0];
    const float* gt   = (const float*)d_in[1];
    float* out        = (float*)d_out;

    static int configured = 0;
    if (!configured) {
        cudaFuncSetAttribute(cd_build, cudaFuncAttributeMaxDynamicSharedMemorySize,
                             GB3 * (int)sizeof(int));
        configured = 1;
    }

    cd_build<<<NGRIDS, 1024, GB3 * sizeof(int)>>>(pred, gt);
    cd_query<<<QGRID, QBLK>>>(out);
}